// round 12
// baseline (speedup 1.0000x reference)
#include <cuda_runtime.h>
#include <cuda_fp16.h>
#include <cstdint>
#include <math.h>

#define N_TOT 262144
#define E_DIM 512
#define H_DIM 256
#define B_BAGS 512

// Scratch (allocation-free rule: __device__ globals)
__device__ float g_sum_alpha[B_BAGS];
__device__ float g_bag_sum[B_BAGS * E_DIM];
__device__ __half g_wh[H_DIM * E_DIM];   // Vw pre-converted to fp16 (256 KB)

// ============================================================================
// helpers
// ============================================================================
__device__ __forceinline__ uint32_t smem_to_u32(const void* p) {
    uint32_t a;
    asm("{ .reg .u64 t; cvta.to.shared.u64 t, %1; cvt.u32.u64 %0, t; }" : "=r"(a) : "l"(p));
    return a;
}
#define LDM_X4(r0_, r1_, r2_, r3_, addr) \
    asm volatile("ldmatrix.sync.aligned.m8n8.x4.shared.b16 {%0,%1,%2,%3}, [%4];" \
                 : "=r"(r0_), "=r"(r1_), "=r"(r2_), "=r"(r3_) : "r"(addr))
#define STS128(addr, a, b, c, d) \
    asm volatile("st.shared.v4.b32 [%0], {%1,%2,%3,%4};" \
                 :: "r"(addr), "r"(a), "r"(b), "r"(c), "r"(d) : "memory")
#define CP_ASYNC16(dst_u32, src_ptr) \
    asm volatile("cp.async.cg.shared.global [%0], [%1], 16;" :: "r"(dst_u32), "l"(src_ptr))
#define CP_COMMIT() asm volatile("cp.async.commit_group;" ::: "memory")
#define CP_WAIT(n)  asm volatile("cp.async.wait_group %0;" :: "n"(n) : "memory")

// fp16-accumulate mma: D(f16x2 pair) = A@B + C
__device__ __forceinline__ void mma_f16acc(uint32_t* c, const uint32_t* a, const uint32_t* b) {
    asm volatile(
        "mma.sync.aligned.m16n8k16.row.col.f16.f16.f16.f16 "
        "{%0,%1}, {%2,%3,%4,%5}, {%6,%7}, {%0,%1};"
        : "+r"(c[0]), "+r"(c[1])
        : "r"(a[0]), "r"(a[1]), "r"(a[2]), "r"(a[3]), "r"(b[0]), "r"(b[1]));
}
__device__ __forceinline__ uint32_t pack2(float lo, float hi) {
    __half2 h = __floats2half2_rn(lo, hi);
    return *reinterpret_cast<uint32_t*>(&h);
}

// ============================================================================
// K1 geometry: CTA = 128(M) x 256(H) x K512 fp16 mma (fp16 accum), 16 stages.
// A tile fully resident (16 slices, register-staged cvt). B: cp.async fp16,
// triple-buffered with 2-stage lookahead (two barriers per stage — the second
// barrier is what makes issue_B(s+3) legal and preserves the lookahead).
// Row stride 80B (conflict-free ldmatrix phases, 16B-aligned STS.128).
// ============================================================================
#define STAGES 16
#define AB_STRIDE 80
#define A_SLICE (128 * AB_STRIDE)        // 10240
#define SM_A 0
#define SM_B (STAGES * A_SLICE)          // 163840
#define B_BUF (256 * AB_STRIDE)          // 20480
#define SM_TOTAL (SM_B + 3 * B_BUF)      // 225280

// kinit: zero accumulators + convert Vw fp32->fp16 (one kernel)
__global__ __launch_bounds__(256)
void kinit(const float* __restrict__ Vw) {
    int i = blockIdx.x * blockDim.x + threadIdx.x;   // 65536 threads
    ((float4*)g_bag_sum)[i] = make_float4(0.f, 0.f, 0.f, 0.f);
    if (i < B_BAGS) g_sum_alpha[i] = 0.0f;
    if (i < H_DIM * E_DIM / 8) {
        const float4* src = (const float4*)Vw;
        float4 a = src[i * 2], b = src[i * 2 + 1];
        uint32_t p[4] = {pack2(a.x, a.y), pack2(a.z, a.w), pack2(b.x, b.y), pack2(b.z, b.w)};
        *(uint4*)(g_wh + (size_t)i * 8) = *(uint4*)p;
    }
}

__device__ __forceinline__ void issue_B(uint32_t sb, int s, int t) {
    const uint32_t bbase = sb + SM_B + (uint32_t)((s % 3) * B_BUF);
#pragma unroll
    for (int i = 0; i < 2; i++) {
        int u = t + i * 512;                // 0..1023 : 256 rows x 4 segs
        int br = u >> 2, seg = u & 3;
        CP_ASYNC16(bbase + (uint32_t)(br * AB_STRIDE + seg * 16),
                   (const void*)(g_wh + (size_t)br * E_DIM + s * 32 + seg * 8));
    }
    CP_COMMIT();
}

__global__ __launch_bounds__(512, 1)
void k1_score(const float* __restrict__ x,    // [N, E]
              const float* __restrict__ Vb,   // [H]
              const float* __restrict__ ww,   // [1, H]
              const float* __restrict__ wb,   // [1]
              const int*   __restrict__ bidx) // [N]
{
    extern __shared__ char smem[];
    __shared__ float s_red[128];
    __shared__ float s_alpha[128];
    __shared__ int   s_bag[128];

    const uint32_t sb = smem_to_u32(smem);
    const int t    = threadIdx.x;
    const int wid  = t >> 5;
    const int lane = t & 31;
    const int q    = lane >> 2;
    const int rr   = lane & 3;
    const int wm   = wid >> 3;      // 0..1 : rows [wm*64, +64)
    const int wn   = wid & 7;       // 0..7 : cols [wn*32, +32)
    const int r0   = blockIdx.x * 128;

    const float4* x4 = (const float4*)x;
    const int arow = t >> 2, aseg = t & 3;   // A: 128 rows x 4 x 16B(fp16)

    uint32_t acc[4][4][2];          // fp16x2 accumulators: [0]=row q, [1]=row q+8
#pragma unroll
    for (int mt = 0; mt < 4; mt++)
#pragma unroll
        for (int nt = 0; nt < 4; nt++) {
            acc[mt][nt][0] = 0u;
            acc[mt][nt][1] = 0u;
        }

    const uint32_t a_lo = (uint32_t)((lane & 15) * AB_STRIDE + ((lane >> 4) << 4));
    const uint32_t b_lo = (uint32_t)(((lane & 7) + ((lane >> 4) & 1) * 8) * AB_STRIDE +
                                     (((lane >> 3) & 1) << 4));

    // ---- prologue: B groups 0,1,2; A0 -> smem; A1 -> regs; s_red init ----
    issue_B(sb, 0, t);
    issue_B(sb, 1, t);
    issue_B(sb, 2, t);
    float4 ha0, ha1;
    {
        ha0 = x4[(size_t)(r0 + arow) * 128 + 0 * 8 + aseg * 2];
        ha1 = x4[(size_t)(r0 + arow) * 128 + 0 * 8 + aseg * 2 + 1];
        uint32_t ad = sb + SM_A + (uint32_t)(0 * A_SLICE + arow * AB_STRIDE + aseg * 16);
        STS128(ad, pack2(ha0.x, ha0.y), pack2(ha0.z, ha0.w),
                   pack2(ha1.x, ha1.y), pack2(ha1.z, ha1.w));
        ha0 = x4[(size_t)(r0 + arow) * 128 + 1 * 8 + aseg * 2];
        ha1 = x4[(size_t)(r0 + arow) * 128 + 1 * 8 + aseg * 2 + 1];
    }
    if (t < 128) s_red[t] = 0.0f;

    for (int s = 0; s < STAGES; s++) {
        // B(s) landed. Tail-exact waits (issuance stops at group 15).
        if (s < STAGES - 2)      { CP_WAIT(2); }
        else if (s == STAGES - 2){ CP_WAIT(1); }
        else                     { CP_WAIT(0); }

        if (s + 1 < STAGES) {                // STS A s+1 from held regs
            uint32_t ad = sb + SM_A + (uint32_t)((s + 1) * A_SLICE + arow * AB_STRIDE + aseg * 16);
            STS128(ad, pack2(ha0.x, ha0.y), pack2(ha0.z, ha0.w),
                       pack2(ha1.x, ha1.y), pack2(ha1.z, ha1.w));
        }
        __syncthreads();                     // A s+1 + B s visible to all
        if (s + 2 < STAGES) {                // LDG A s+2 (in flight across compute)
            ha0 = x4[(size_t)(r0 + arow) * 128 + (s + 2) * 8 + aseg * 2];
            ha1 = x4[(size_t)(r0 + arow) * 128 + (s + 2) * 8 + aseg * 2 + 1];
        }

        // ---- compute stage s ----
        const uint32_t ab = sb + SM_A + (uint32_t)(s * A_SLICE);
        const uint32_t bb = sb + SM_B + (uint32_t)((s % 3) * B_BUF);
#pragma unroll
        for (int k16 = 0; k16 < 2; k16++) {
            const uint32_t kof = (uint32_t)(k16 * 32);
            uint32_t af[4][4];
#pragma unroll
            for (int mt = 0; mt < 4; mt++)
                LDM_X4(af[mt][0], af[mt][1], af[mt][2], af[mt][3],
                       ab + (uint32_t)((wm * 64 + mt * 16) * AB_STRIDE) + kof + a_lo);
            uint32_t bf[4][2];
#pragma unroll
            for (int pr = 0; pr < 2; pr++) {
                uint32_t f0, f1, f2, f3;
                LDM_X4(f0, f1, f2, f3,
                       bb + (uint32_t)((wn * 32 + pr * 16) * AB_STRIDE) + kof + b_lo);
                bf[2 * pr][0] = f0; bf[2 * pr][1] = f1;
                bf[2 * pr + 1][0] = f2; bf[2 * pr + 1][1] = f3;
            }
#pragma unroll
            for (int mt = 0; mt < 4; mt++)
#pragma unroll
                for (int nt = 0; nt < 4; nt++)
                    mma_f16acc(acc[mt][nt], af[mt], bf[nt]);
        }
        if (s + 3 < STAGES) {
            __syncthreads();                 // all warps done with B buf s%3
            issue_B(sb, s + 3, t);           // refill it (2-stage lookahead)
        }
    }

    // ---------------- epilogue: scores ----------------
    float vb[4][2], wv[4][2];
#pragma unroll
    for (int nt = 0; nt < 4; nt++)
#pragma unroll
        for (int j = 0; j < 2; j++) {
            int c = wn * 32 + nt * 8 + 2 * rr + j;
            vb[nt][j] = Vb[c];
            wv[nt][j] = ww[c];
        }

#pragma unroll
    for (int mt = 0; mt < 4; mt++) {
        float plo = 0.0f, phi = 0.0f;
#pragma unroll
        for (int nt = 0; nt < 4; nt++) {
            __half2 hq  = *reinterpret_cast<__half2*>(&acc[mt][nt][0]);  // row q  cols 2rr,2rr+1
            __half2 hq8 = *reinterpret_cast<__half2*>(&acc[mt][nt][1]);  // row q+8
            float cq[2]  = {__low2float(hq),  __high2float(hq)};
            float cq8[2] = {__low2float(hq8), __high2float(hq8)};
#pragma unroll
            for (int j = 0; j < 2; j++) {
                float tlo, thi;
                asm("tanh.approx.f32 %0, %1;" : "=f"(tlo) : "f"(cq[j]  + vb[nt][j]));
                asm("tanh.approx.f32 %0, %1;" : "=f"(thi) : "f"(cq8[j] + vb[nt][j]));
                plo = fmaf(tlo, wv[nt][j], plo);
                phi = fmaf(thi, wv[nt][j], phi);
            }
        }
        plo += __shfl_xor_sync(0xFFFFFFFFu, plo, 1);
        plo += __shfl_xor_sync(0xFFFFFFFFu, plo, 2);
        phi += __shfl_xor_sync(0xFFFFFFFFu, phi, 1);
        phi += __shfl_xor_sync(0xFFFFFFFFu, phi, 2);
        if (rr == 0) {
            int row = wm * 64 + mt * 16 + q;
            atomicAdd(&s_red[row], plo);
            atomicAdd(&s_red[row + 8], phi);
        }
    }
    __syncthreads();

    if (t < 128) {
        int r = r0 + t;
        int b = bidx[r];
        float al = expf(s_red[t] + wb[0]);
        s_alpha[t] = al;
        s_bag[t]   = b;
        atomicAdd(&g_sum_alpha[b], al);
    }
    __syncthreads();

    // ---------------- fused pooling (x tile resident as fp16) ----------------
    {
        const __half* hp = (const __half*)(smem + (t >> 5) * A_SLICE + (t & 31) * 2);
        float accp = 0.0f;
        int cur = s_bag[0];
#pragma unroll 4
        for (int r = 0; r < 128; r++) {
            int b = s_bag[r];
            if (b != cur) {
                atomicAdd(&g_bag_sum[(size_t)cur * E_DIM + t], accp);
                accp = 0.0f;
                cur = b;
            }
            accp = fmaf(s_alpha[r], __half2float(hp[r * (AB_STRIDE / 2)]), accp);
        }
        atomicAdd(&g_bag_sum[(size_t)cur * E_DIM + t], accp);
    }
}

// ---------------------------------------------------------------------------
// K3: logits + 2-way softmax; warp per bag, float4 loads (4-way MLP)
// ---------------------------------------------------------------------------
__global__ __launch_bounds__(256)
void k3_logits(const float* __restrict__ dw, const float* __restrict__ db,
               float* __restrict__ out)
{
    int warp = (blockIdx.x * blockDim.x + threadIdx.x) >> 5;
    int lane = threadIdx.x & 31;
    if (warp >= B_BAGS) return;

    const float4* bs4 = (const float4*)(g_bag_sum + (size_t)warp * E_DIM);
    const float4* dw4 = (const float4*)dw;   // [2][128]
    float s0 = 0.0f, s1 = 0.0f;
#pragma unroll
    for (int i = 0; i < 4; i++) {
        float4 b  = bs4[lane + 32 * i];
        float4 w0 = dw4[lane + 32 * i];
        float4 w1 = dw4[128 + lane + 32 * i];
        s0 += b.x * w0.x + b.y * w0.y + b.z * w0.z + b.w * w0.w;
        s1 += b.x * w1.x + b.y * w1.y + b.z * w1.z + b.w * w1.w;
    }
#pragma unroll
    for (int off = 16; off > 0; off >>= 1) {
        s0 += __shfl_xor_sync(0xFFFFFFFFu, s0, off);
        s1 += __shfl_xor_sync(0xFFFFFFFFu, s1, off);
    }
    if (lane == 0) {
        float inv = 1.0f / g_sum_alpha[warp];
        float l0 = fmaf(s0, inv, db[0]);
        float l1 = fmaf(s1, inv, db[1]);
        float m = fmaxf(l0, l1);
        float e0 = expf(l0 - m), e1 = expf(l1 - m);
        float d = e0 + e1;
        out[warp * 2 + 0] = e0 / d;
        out[warp * 2 + 1] = e1 / d;
    }
}

// ---------------------------------------------------------------------------
extern "C" void kernel_launch(void* const* d_in, const int* in_sizes, int n_in,
                              void* d_out, int out_size)
{
    const float* x    = (const float*)d_in[0];
    const float* Vw   = (const float*)d_in[1];
    const float* Vb   = (const float*)d_in[2];
    const float* ww   = (const float*)d_in[3];
    const float* wb   = (const float*)d_in[4];
    const float* dw   = (const float*)d_in[5];
    const float* db   = (const float*)d_in[6];
    const int*   bidx = (const int*)d_in[7];
    float* out = (float*)d_out;

    static int smem_set = 0;
    if (!smem_set) {
        cudaFuncSetAttribute(k1_score, cudaFuncAttributeMaxDynamicSharedMemorySize, SM_TOTAL);
        smem_set = 1;
    }

    kinit<<<B_BAGS * E_DIM / 4 / 256, 256>>>(Vw);
    k1_score<<<N_TOT / 128, 512, SM_TOTAL>>>(x, Vb, ww, wb, bidx);
    k3_logits<<<(B_BAGS * 32 + 255) / 256, 256>>>(dw, db, out);
}

// round 13
// speedup vs baseline: 1.1808x; 1.1808x over previous
#include <cuda_runtime.h>
#include <cuda_fp16.h>
#include <cstdint>
#include <math.h>

#define N_TOT 262144
#define E_DIM 512
#define H_DIM 256
#define B_BAGS 512

// Scratch (allocation-free rule: __device__ globals)
__device__ float g_sum_alpha[B_BAGS];
__device__ float g_bag_sum[B_BAGS * E_DIM];
__device__ __half g_wh[H_DIM * E_DIM];   // Vw pre-converted to fp16 (256 KB)

// ============================================================================
// helpers
// ============================================================================
__device__ __forceinline__ uint32_t smem_to_u32(const void* p) {
    uint32_t a;
    asm("{ .reg .u64 t; cvta.to.shared.u64 t, %1; cvt.u32.u64 %0, t; }" : "=r"(a) : "l"(p));
    return a;
}
#define LDM_X4(r0_, r1_, r2_, r3_, addr) \
    asm volatile("ldmatrix.sync.aligned.m8n8.x4.shared.b16 {%0,%1,%2,%3}, [%4];" \
                 : "=r"(r0_), "=r"(r1_), "=r"(r2_), "=r"(r3_) : "r"(addr))
#define STS128(addr, a, b, c, d) \
    asm volatile("st.shared.v4.b32 [%0], {%1,%2,%3,%4};" \
                 :: "r"(addr), "r"(a), "r"(b), "r"(c), "r"(d) : "memory")
#define CP_ASYNC16(dst_u32, src_ptr) \
    asm volatile("cp.async.cg.shared.global [%0], [%1], 16;" :: "r"(dst_u32), "l"(src_ptr))
#define CP_COMMIT() asm volatile("cp.async.commit_group;" ::: "memory")
#define CP_WAIT(n)  asm volatile("cp.async.wait_group %0;" :: "n"(n) : "memory")

// fp16-accumulate mma: D(f16x2 pair) = A@B + C
__device__ __forceinline__ void mma_f16acc(uint32_t* c, const uint32_t* a, const uint32_t* b) {
    asm volatile(
        "mma.sync.aligned.m16n8k16.row.col.f16.f16.f16.f16 "
        "{%0,%1}, {%2,%3,%4,%5}, {%6,%7}, {%0,%1};"
        : "+r"(c[0]), "+r"(c[1])
        : "r"(a[0]), "r"(a[1]), "r"(a[2]), "r"(a[3]), "r"(b[0]), "r"(b[1]));
}
__device__ __forceinline__ uint32_t pack2(float lo, float hi) {
    __half2 h = __floats2half2_rn(lo, hi);
    return *reinterpret_cast<uint32_t*>(&h);
}

// XOR-swizzled 64B-row layout: row r, 16B-seg seg(0..3).
// Conflict-free for ldmatrix 8-row phases and STS.128 (zero padding).
__device__ __forceinline__ uint32_t swz(uint32_t row, uint32_t seg) {
    return row * 64 + (((seg ^ ((row >> 1) & 3)) & 3) << 4);
}

// ============================================================================
// K1 geometry: CTA = 64(M) x 256(H) x K512, fp16 mma (fp16 accum), 16 stages.
// 256 threads / 8 warps; 2 CTAs per SM (96 KB dynamic smem).
// A tile fully resident (16 swizzled 4KB slices); B double-buffered cp.async.
// ============================================================================
#define TILE_M 64
#define STAGES 16
#define A_SLICE (TILE_M * 64)            // 4096
#define SM_A 0
#define SM_B (STAGES * A_SLICE)          // 65536
#define B_BUF (H_DIM * 64)               // 16384
#define SM_TOTAL (SM_B + 2 * B_BUF)      // 98304

// kinit: zero accumulators + convert Vw fp32->fp16 (one kernel)
__global__ __launch_bounds__(256)
void kinit(const float* __restrict__ Vw) {
    int i = blockIdx.x * blockDim.x + threadIdx.x;   // 65536 threads
    ((float4*)g_bag_sum)[i] = make_float4(0.f, 0.f, 0.f, 0.f);
    if (i < B_BAGS) g_sum_alpha[i] = 0.0f;
    if (i < H_DIM * E_DIM / 8) {
        const float4* src = (const float4*)Vw;
        float4 a = src[i * 2], b = src[i * 2 + 1];
        uint32_t p[4] = {pack2(a.x, a.y), pack2(a.z, a.w), pack2(b.x, b.y), pack2(b.z, b.w)};
        *(uint4*)(g_wh + (size_t)i * 8) = *(uint4*)p;
    }
}

__device__ __forceinline__ void issue_B(uint32_t sb, int s, int t) {
    const uint32_t bbase = sb + SM_B + (uint32_t)((s & 1) * B_BUF);
#pragma unroll
    for (int i = 0; i < 4; i++) {
        int u = t + i * 256;                // 0..1023 : 256 rows x 4 segs
        int br = u >> 2, seg = u & 3;
        CP_ASYNC16(bbase + swz((uint32_t)br, (uint32_t)seg),
                   (const void*)(g_wh + (size_t)br * E_DIM + s * 32 + seg * 8));
    }
    CP_COMMIT();
}

__global__ __launch_bounds__(256, 2)
void k1_score(const float* __restrict__ x,    // [N, E]
              const float* __restrict__ Vb,   // [H]
              const float* __restrict__ ww,   // [1, H]
              const float* __restrict__ wb,   // [1]
              const int*   __restrict__ bidx) // [N]
{
    extern __shared__ char smem[];
    __shared__ float s_red[TILE_M];
    __shared__ float s_alpha[TILE_M];
    __shared__ int   s_bag[TILE_M];

    const uint32_t sb = smem_to_u32(smem);
    const int t    = threadIdx.x;
    const int wid  = t >> 5;        // 0..7 = wn : cols [wn*32, +32)
    const int lane = t & 31;
    const int q    = lane >> 2;
    const int rr   = lane & 3;
    const int wn   = wid;
    const int r0   = blockIdx.x * TILE_M;

    const float4* x4 = (const float4*)x;
    const int arow = t >> 2, aseg = t & 3;   // A: 64 rows x 4 x 16B(fp16)

    uint32_t acc[4][4][2];          // fp16x2 accumulators: [0]=row q, [1]=row q+8
#pragma unroll
    for (int mt = 0; mt < 4; mt++)
#pragma unroll
        for (int nt = 0; nt < 4; nt++) {
            acc[mt][nt][0] = 0u;
            acc[mt][nt][1] = 0u;
        }

    // swizzled per-lane ldmatrix offsets, per k16 half
    uint32_t a_off[2], b_off[2];
    {
        uint32_t r_la = (uint32_t)(lane & 15);
        uint32_t r_lb = (uint32_t)((lane & 7) + ((lane >> 4) & 1) * 8);
#pragma unroll
        for (int k16 = 0; k16 < 2; k16++) {
            a_off[k16] = swz(r_la, (uint32_t)(2 * k16 + (lane >> 4)));
            b_off[k16] = swz(r_lb, (uint32_t)(2 * k16 + ((lane >> 3) & 1)));
        }
    }

    // ---- prologue: B groups 0,1; A0 -> smem; A1 -> regs; s_red init ----
    issue_B(sb, 0, t);
    issue_B(sb, 1, t);
    float4 ha0, ha1;
    {
        ha0 = x4[(size_t)(r0 + arow) * 128 + 0 * 8 + aseg * 2];
        ha1 = x4[(size_t)(r0 + arow) * 128 + 0 * 8 + aseg * 2 + 1];
        uint32_t ad = sb + SM_A + 0 * A_SLICE + swz((uint32_t)arow, (uint32_t)aseg);
        STS128(ad, pack2(ha0.x, ha0.y), pack2(ha0.z, ha0.w),
                   pack2(ha1.x, ha1.y), pack2(ha1.z, ha1.w));
        ha0 = x4[(size_t)(r0 + arow) * 128 + 1 * 8 + aseg * 2];
        ha1 = x4[(size_t)(r0 + arow) * 128 + 1 * 8 + aseg * 2 + 1];
    }
    if (t < TILE_M) s_red[t] = 0.0f;

    for (int s = 0; s < STAGES; s++) {
        if (s < STAGES - 1) { CP_WAIT(1); } else { CP_WAIT(0); }   // B(s) landed

        if (s + 1 < STAGES) {                // STS A s+1 from held regs
            uint32_t ad = sb + SM_A + (uint32_t)((s + 1) * A_SLICE) +
                          swz((uint32_t)arow, (uint32_t)aseg);
            STS128(ad, pack2(ha0.x, ha0.y), pack2(ha0.z, ha0.w),
                       pack2(ha1.x, ha1.y), pack2(ha1.z, ha1.w));
        }
        __syncthreads();                     // A s+1 + B s visible to all
        if (s + 2 < STAGES) {                // LDG A s+2 (in flight across compute)
            ha0 = x4[(size_t)(r0 + arow) * 128 + (s + 2) * 8 + aseg * 2];
            ha1 = x4[(size_t)(r0 + arow) * 128 + (s + 2) * 8 + aseg * 2 + 1];
        }

        // ---- compute stage s ----
        const uint32_t ab = sb + SM_A + (uint32_t)(s * A_SLICE);
        const uint32_t bb = sb + SM_B + (uint32_t)((s & 1) * B_BUF);
#pragma unroll
        for (int k16 = 0; k16 < 2; k16++) {
            uint32_t af[4][4];
#pragma unroll
            for (int mt = 0; mt < 4; mt++)
                LDM_X4(af[mt][0], af[mt][1], af[mt][2], af[mt][3],
                       ab + (uint32_t)(mt * 1024) + a_off[k16]);
            uint32_t bf[4][2];
#pragma unroll
            for (int pr = 0; pr < 2; pr++) {
                uint32_t f0, f1, f2, f3;
                LDM_X4(f0, f1, f2, f3,
                       bb + (uint32_t)(wn * 2048 + pr * 1024) + b_off[k16]);
                bf[2 * pr][0] = f0; bf[2 * pr][1] = f1;
                bf[2 * pr + 1][0] = f2; bf[2 * pr + 1][1] = f3;
            }
#pragma unroll
            for (int mt = 0; mt < 4; mt++)
#pragma unroll
                for (int nt = 0; nt < 4; nt++)
                    mma_f16acc(acc[mt][nt], af[mt], bf[nt]);
        }
        if (s + 2 < STAGES) {
            __syncthreads();                 // all warps done with B buf s&1
            issue_B(sb, s + 2, t);           // refill it
        }
    }

    // ---------------- epilogue: scores ----------------
    float vb[4][2], wv[4][2];
#pragma unroll
    for (int nt = 0; nt < 4; nt++)
#pragma unroll
        for (int j = 0; j < 2; j++) {
            int c = wn * 32 + nt * 8 + 2 * rr + j;
            vb[nt][j] = Vb[c];
            wv[nt][j] = ww[c];
        }

#pragma unroll
    for (int mt = 0; mt < 4; mt++) {
        float plo = 0.0f, phi = 0.0f;
#pragma unroll
        for (int nt = 0; nt < 4; nt++) {
            __half2 hq  = *reinterpret_cast<__half2*>(&acc[mt][nt][0]);  // row q
            __half2 hq8 = *reinterpret_cast<__half2*>(&acc[mt][nt][1]);  // row q+8
            float cq[2]  = {__low2float(hq),  __high2float(hq)};
            float cq8[2] = {__low2float(hq8), __high2float(hq8)};
#pragma unroll
            for (int j = 0; j < 2; j++) {
                float tlo, thi;
                asm("tanh.approx.f32 %0, %1;" : "=f"(tlo) : "f"(cq[j]  + vb[nt][j]));
                asm("tanh.approx.f32 %0, %1;" : "=f"(thi) : "f"(cq8[j] + vb[nt][j]));
                plo = fmaf(tlo, wv[nt][j], plo);
                phi = fmaf(thi, wv[nt][j], phi);
            }
        }
        plo += __shfl_xor_sync(0xFFFFFFFFu, plo, 1);
        plo += __shfl_xor_sync(0xFFFFFFFFu, plo, 2);
        phi += __shfl_xor_sync(0xFFFFFFFFu, phi, 1);
        phi += __shfl_xor_sync(0xFFFFFFFFu, phi, 2);
        if (rr == 0) {
            int row = mt * 16 + q;
            atomicAdd(&s_red[row], plo);
            atomicAdd(&s_red[row + 8], phi);
        }
    }
    __syncthreads();

    if (t < TILE_M) {
        int r = r0 + t;
        int b = bidx[r];
        float al = expf(s_red[t] + wb[0]);
        s_alpha[t] = al;
        s_bag[t]   = b;
        atomicAdd(&g_sum_alpha[b], al);
    }
    __syncthreads();

    // ---------------- fused pooling (x tile resident as fp16, swizzled) ------
    // thread t owns columns e = 2t, 2t+1 (one __half2 per row).
    {
        const uint32_t slice = (uint32_t)(t >> 4);         // (2t)>>5
        const uint32_t segp  = (uint32_t)((t & 15) >> 2);  // 16B seg
        const uint32_t inner = (uint32_t)((t & 3) * 4);    // byte within seg
        float acc0 = 0.0f, acc1 = 0.0f;
        int cur = s_bag[0];
#pragma unroll 4
        for (int r = 0; r < TILE_M; r++) {
            int b = s_bag[r];
            if (b != cur) {
                atomicAdd(&g_bag_sum[(size_t)cur * E_DIM + 2 * t],     acc0);
                atomicAdd(&g_bag_sum[(size_t)cur * E_DIM + 2 * t + 1], acc1);
                acc0 = acc1 = 0.0f;
                cur = b;
            }
            uint32_t off = slice * A_SLICE + swz((uint32_t)r, segp) + inner;
            __half2 hv = *reinterpret_cast<const __half2*>(smem + off);
            float al = s_alpha[r];
            acc0 = fmaf(al, __low2float(hv),  acc0);
            acc1 = fmaf(al, __high2float(hv), acc1);
        }
        atomicAdd(&g_bag_sum[(size_t)cur * E_DIM + 2 * t],     acc0);
        atomicAdd(&g_bag_sum[(size_t)cur * E_DIM + 2 * t + 1], acc1);
    }
}

// ---------------------------------------------------------------------------
// K3: logits + 2-way softmax; warp per bag, float4 loads (4-way MLP)
// ---------------------------------------------------------------------------
__global__ __launch_bounds__(256)
void k3_logits(const float* __restrict__ dw, const float* __restrict__ db,
               float* __restrict__ out)
{
    int warp = (blockIdx.x * blockDim.x + threadIdx.x) >> 5;
    int lane = threadIdx.x & 31;
    if (warp >= B_BAGS) return;

    const float4* bs4 = (const float4*)(g_bag_sum + (size_t)warp * E_DIM);
    const float4* dw4 = (const float4*)dw;   // [2][128]
    float s0 = 0.0f, s1 = 0.0f;
#pragma unroll
    for (int i = 0; i < 4; i++) {
        float4 b  = bs4[lane + 32 * i];
        float4 w0 = dw4[lane + 32 * i];
        float4 w1 = dw4[128 + lane + 32 * i];
        s0 += b.x * w0.x + b.y * w0.y + b.z * w0.z + b.w * w0.w;
        s1 += b.x * w1.x + b.y * w1.y + b.z * w1.z + b.w * w1.w;
    }
#pragma unroll
    for (int off = 16; off > 0; off >>= 1) {
        s0 += __shfl_xor_sync(0xFFFFFFFFu, s0, off);
        s1 += __shfl_xor_sync(0xFFFFFFFFu, s1, off);
    }
    if (lane == 0) {
        float inv = 1.0f / g_sum_alpha[warp];
        float l0 = fmaf(s0, inv, db[0]);
        float l1 = fmaf(s1, inv, db[1]);
        float m = fmaxf(l0, l1);
        float e0 = expf(l0 - m), e1 = expf(l1 - m);
        float d = e0 + e1;
        out[warp * 2 + 0] = e0 / d;
        out[warp * 2 + 1] = e1 / d;
    }
}

// ---------------------------------------------------------------------------
extern "C" void kernel_launch(void* const* d_in, const int* in_sizes, int n_in,
                              void* d_out, int out_size)
{
    const float* x    = (const float*)d_in[0];
    const float* Vw   = (const float*)d_in[1];
    const float* Vb   = (const float*)d_in[2];
    const float* ww   = (const float*)d_in[3];
    const float* wb   = (const float*)d_in[4];
    const float* dw   = (const float*)d_in[5];
    const float* db   = (const float*)d_in[6];
    const int*   bidx = (const int*)d_in[7];
    float* out = (float*)d_out;

    static int smem_set = 0;
    if (!smem_set) {
        cudaFuncSetAttribute(k1_score, cudaFuncAttributeMaxDynamicSharedMemorySize, SM_TOTAL);
        smem_set = 1;
    }

    kinit<<<B_BAGS * E_DIM / 4 / 256, 256>>>(Vw);
    k1_score<<<N_TOT / TILE_M, 256, SM_TOTAL>>>(x, Vb, ww, wb, bidx);
    k3_logits<<<(B_BAGS * 32 + 255) / 256, 256>>>(dw, db, out);
}